// round 1
// baseline (speedup 1.0000x reference)
#include <cuda_runtime.h>
#include <cuda_bf16.h>

// Problem constants
#define NGROUPS 8
#define CIN 4
#define COUT 4
#define KSIZE 5
#define NPART 8
#define B_    8
#define H_    256
#define W_    512
#define CI_   32
#define CO_   32
#define HP_   32      // H_/NPART rows per slab

// Tile config
#define TX 64         // output cols per block
#define TY 4          // output rows per block
#define XS 8          // cols per thread
#define NTHREADS 256  // 32 co * 8 xsub

#define NTAPS 13
#define SIN_ROWS 6            // TY + 2
#define SIN_COLS 68           // TX + 4
#define SIN_ELEMS (CI_ * SIN_ROWS * SIN_COLS)       // 13056
#define SW_ELEMS  (CI_ * NTAPS * CO_)               // 13312
#define SMEM_BYTES ((SIN_ELEMS + SW_ELEMS) * 4)     // 105472

// Masked-weight scratch: layout [ci][tap][co]
__device__ float g_w[SW_ELEMS];

// ---------------------------------------------------------------------------
// Prep: apply PixelCNN group mask (HIDDEN=True: center visible iff gin<=gout)
// and reorder weights to [ci][tap][co].
// tap 0..9  -> ky=tap/5 (0,1), kx=tap%5
// tap 10,11 -> ky=2, kx=0,1
// tap 12    -> ky=2, kx=2 (center, group-gated)
// ---------------------------------------------------------------------------
__global__ void prep_weights(const float* __restrict__ w) {
    int i = blockIdx.x * blockDim.x + threadIdx.x;
    if (i >= SW_ELEMS) return;
    int co = i & 31;
    int k  = (i >> 5) % NTAPS;
    int ci = i / (NTAPS * CO_);
    int ky, kx;
    float m = 1.0f;
    if (k < 10)      { ky = k / 5; kx = k % 5; }
    else if (k == 10){ ky = 2; kx = 0; }
    else if (k == 11){ ky = 2; kx = 1; }
    else             { ky = 2; kx = 2; m = ((ci >> 2) <= (co >> 2)) ? 1.0f : 0.0f; }
    g_w[i] = w[((co * CI_ + ci) * KSIZE + ky) * KSIZE + kx] * m;
}

// ---------------------------------------------------------------------------
// Main conv kernel. Grid: (W/TX=8, HP/TY=8, B*NPART=64). Block: 256 threads.
// ---------------------------------------------------------------------------
extern __shared__ float smem[];

__global__ void __launch_bounds__(NTHREADS, 2)
conv_kernel(const float* __restrict__ x,
            const float* __restrict__ bias,
            const float* __restrict__ alpha,
            const int*   __restrict__ widths,
            float* __restrict__ out)
{
    const int tile_x = blockIdx.x;
    const int tile_y = blockIdx.y;
    const int slab   = blockIdx.z;
    const int b      = slab >> 3;
    const int part   = slab & 7;
    const int width  = widths[part];
    const int x0     = tile_x * TX;
    const int y0     = tile_y * TY;          // local row in slab
    const int gy0    = part * HP_ + y0;      // global row

    const int t    = threadIdx.x;
    const int xsub = t & 7;
    const int co   = t >> 3;
    const int xoff = xsub * XS;

    // ---- fast path: whole tile past the valid width -> zeros ----
    if (x0 >= width) {
        const float4 z = make_float4(0.f, 0.f, 0.f, 0.f);
        #pragma unroll
        for (int o = 0; o < TY; ++o) {
            int base = ((b * CO_ + co) * H_ + gy0 + o) * W_ + x0 + xoff;
            *(float4*)(out + base)     = z;
            *(float4*)(out + base + 4) = z;
        }
        return;
    }

    float* sIn = smem;                 // [ci][6][68]
    float* sW  = smem + SIN_ELEMS;     // [ci][13][co]

    // ---- stage weights ----
    #pragma unroll
    for (int i = t; i < SW_ELEMS; i += NTHREADS) sW[i] = g_w[i];

    // ---- stage input tile (masked: slab-local rows, col < width) ----
    const int wlim = (width < W_) ? width : W_;
    for (int i = t; i < SIN_ELEMS; i += NTHREADS) {
        int c  = i % SIN_COLS;
        int rr = i / SIN_COLS;
        int r  = rr % SIN_ROWS;
        int ci = rr / SIN_ROWS;
        int ly = y0 - 2 + r;          // local row in slab (pad outside)
        int gx = x0 - 2 + c;
        float v = 0.f;
        if (ly >= 0 && ly < HP_ && gx >= 0 && gx < wlim) {
            v = x[((b * CI_ + ci) * H_ + part * HP_ + ly) * W_ + gx];
        }
        sIn[i] = v;
    }
    __syncthreads();

    float acc[TY][XS];
    #pragma unroll
    for (int o = 0; o < TY; ++o)
        #pragma unroll
        for (int j = 0; j < XS; ++j) acc[o][j] = 0.f;

    #pragma unroll 1
    for (int ci = 0; ci < CI_; ++ci) {
        float wgt[NTAPS];
        const float* wp = sW + ci * (NTAPS * CO_) + co;
        #pragma unroll
        for (int k = 0; k < NTAPS; ++k) wgt[k] = wp[k * CO_];

        const float* rb = sIn + ci * (SIN_ROWS * SIN_COLS) + xoff;
        #pragma unroll
        for (int r = 0; r < SIN_ROWS; ++r) {
            float v[12];
            const float4 a0 = *(const float4*)(rb + r * SIN_COLS);
            const float4 a1 = *(const float4*)(rb + r * SIN_COLS + 4);
            const float4 a2 = *(const float4*)(rb + r * SIN_COLS + 8);
            v[0]=a0.x; v[1]=a0.y; v[2]=a0.z; v[3]=a0.w;
            v[4]=a1.x; v[5]=a1.y; v[6]=a1.z; v[7]=a1.w;
            v[8]=a2.x; v[9]=a2.y; v[10]=a2.z; v[11]=a2.w;

            // out row o uses input rows o (ky0), o+1 (ky1), o+2 (ky2);
            // smem row r = input row (y0-2+r), out row o local = y0+o.
            if (r < TY) {                         // ky=0 taps for out row r
                #pragma unroll
                for (int kx = 0; kx < 5; ++kx)
                    #pragma unroll
                    for (int j = 0; j < XS; ++j)
                        acc[r][j] = fmaf(v[j + kx], wgt[kx], acc[r][j]);
            }
            if (r >= 1 && r < TY + 1) {           // ky=1 taps for out row r-1
                #pragma unroll
                for (int kx = 0; kx < 5; ++kx)
                    #pragma unroll
                    for (int j = 0; j < XS; ++j)
                        acc[r-1][j] = fmaf(v[j + kx], wgt[5 + kx], acc[r-1][j]);
            }
            if (r >= 2) {                         // ky=2 taps for out row r-2
                #pragma unroll
                for (int j = 0; j < XS; ++j) {
                    acc[r-2][j] = fmaf(v[j],     wgt[10], acc[r-2][j]);
                    acc[r-2][j] = fmaf(v[j + 1], wgt[11], acc[r-2][j]);
                    acc[r-2][j] = fmaf(v[j + 2], wgt[12], acc[r-2][j]);
                }
            }
        }
    }

    // ---- epilogue: bias, leaky-ReLU, width mask, vectorized store ----
    const float bz = __ldg(bias  + co);
    const float al = __ldg(alpha + co);
    #pragma unroll
    for (int o = 0; o < TY; ++o) {
        float vals[XS];
        #pragma unroll
        for (int j = 0; j < XS; ++j) {
            float y = acc[o][j] + bz;
            y = (y > 0.f) ? y : al * y;
            int gx = x0 + xoff + j;
            vals[j] = (gx < width) ? y : 0.f;
        }
        int base = ((b * CO_ + co) * H_ + gy0 + o) * W_ + x0 + xoff;
        *(float4*)(out + base)     = make_float4(vals[0], vals[1], vals[2], vals[3]);
        *(float4*)(out + base + 4) = make_float4(vals[4], vals[5], vals[6], vals[7]);
    }
}

// ---------------------------------------------------------------------------
// Launch
// ---------------------------------------------------------------------------
extern "C" void kernel_launch(void* const* d_in, const int* in_sizes, int n_in,
                              void* d_out, int out_size)
{
    const float* x      = (const float*)d_in[0];
    const float* weight = (const float*)d_in[1];
    const float* bias   = (const float*)d_in[2];
    const float* alpha  = (const float*)d_in[3];
    const int*   widths = (const int*)  d_in[4];
    float* out = (float*)d_out;

    (void)in_sizes; (void)n_in; (void)out_size;

    cudaFuncSetAttribute(conv_kernel,
                         cudaFuncAttributeMaxDynamicSharedMemorySize,
                         SMEM_BYTES);

    prep_weights<<<(SW_ELEMS + 255) / 256, 256>>>(weight);

    dim3 grid(W_ / TX, HP_ / TY, B_ * NPART);
    conv_kernel<<<grid, NTHREADS, SMEM_BYTES>>>(x, bias, alpha, widths, out);
}

// round 2
// speedup vs baseline: 1.0068x; 1.0068x over previous
#include <cuda_runtime.h>
#include <cuda_bf16.h>

// Problem constants
#define NGROUPS 8
#define CIN 4
#define COUT 4
#define KSIZE 5
#define NPART 8
#define B_    8
#define H_    256
#define W_    512
#define CI_   32
#define CO_   32
#define HP_   32      // H_/NPART rows per slab

// Tile config
#define TX 64         // output cols per block
#define TY 4          // output rows per block
#define XS 8          // cols per thread
#define NTHREADS 256  // 32 co * 8 xsub

#define NTAPS 13
#define SIN_ROWS 6            // TY + 2
#define SIN_COLS 68           // TX + 4
#define SIN_ELEMS (CI_ * SIN_ROWS * SIN_COLS)       // 13056
#define SW_ELEMS  (CI_ * NTAPS * CO_)               // 13312
#define SMEM_BYTES ((SIN_ELEMS + SW_ELEMS) * 4)     // 105472

// Masked-weight scratch: layout [ci][tap][co]
__device__ float g_w[SW_ELEMS];

// ---------------------------------------------------------------------------
// Prep: apply PixelCNN group mask (HIDDEN=True: center visible iff gin<=gout)
// and reorder weights to [ci][tap][co].
// tap 0..9  -> ky=tap/5 (0,1), kx=tap%5
// tap 10,11 -> ky=2, kx=0,1
// tap 12    -> ky=2, kx=2 (center, group-gated)
// ---------------------------------------------------------------------------
__global__ void prep_weights(const float* __restrict__ w) {
    int i = blockIdx.x * blockDim.x + threadIdx.x;
    if (i >= SW_ELEMS) return;
    int co = i & 31;
    int k  = (i >> 5) % NTAPS;
    int ci = i / (NTAPS * CO_);
    int ky, kx;
    float m = 1.0f;
    if (k < 10)      { ky = k / 5; kx = k % 5; }
    else if (k == 10){ ky = 2; kx = 0; }
    else if (k == 11){ ky = 2; kx = 1; }
    else             { ky = 2; kx = 2; m = ((ci >> 2) <= (co >> 2)) ? 1.0f : 0.0f; }
    g_w[i] = w[((co * CI_ + ci) * KSIZE + ky) * KSIZE + kx] * m;
}

// ---------------------------------------------------------------------------
// Main conv kernel. Grid: (W/TX=8, HP/TY=8, B*NPART=64). Block: 256 threads.
// ---------------------------------------------------------------------------
extern __shared__ float smem[];

__global__ void __launch_bounds__(NTHREADS, 2)
conv_kernel(const float* __restrict__ x,
            const float* __restrict__ bias,
            const float* __restrict__ alpha,
            const int*   __restrict__ widths,
            float* __restrict__ out)
{
    const int tile_x = blockIdx.x;
    const int tile_y = blockIdx.y;
    const int slab   = blockIdx.z;
    const int b      = slab >> 3;
    const int part   = slab & 7;
    const int width  = widths[part];
    const int x0     = tile_x * TX;
    const int y0     = tile_y * TY;          // local row in slab
    const int gy0    = part * HP_ + y0;      // global row

    const int t    = threadIdx.x;
    const int xsub = t & 7;
    const int co   = t >> 3;
    const int xoff = xsub * XS;

    // ---- fast path: whole tile past the valid width -> zeros ----
    if (x0 >= width) {
        const float4 z = make_float4(0.f, 0.f, 0.f, 0.f);
        #pragma unroll
        for (int o = 0; o < TY; ++o) {
            int base = ((b * CO_ + co) * H_ + gy0 + o) * W_ + x0 + xoff;
            *(float4*)(out + base)     = z;
            *(float4*)(out + base + 4) = z;
        }
        return;
    }

    float* sIn = smem;                 // [ci][6][68]
    float* sW  = smem + SIN_ELEMS;     // [ci][13][co]

    // ---- stage weights ----
    #pragma unroll
    for (int i = t; i < SW_ELEMS; i += NTHREADS) sW[i] = g_w[i];

    // ---- stage input tile (masked: slab-local rows, col < width) ----
    const int wlim = (width < W_) ? width : W_;
    for (int i = t; i < SIN_ELEMS; i += NTHREADS) {
        int c  = i % SIN_COLS;
        int rr = i / SIN_COLS;
        int r  = rr % SIN_ROWS;
        int ci = rr / SIN_ROWS;
        int ly = y0 - 2 + r;          // local row in slab (pad outside)
        int gx = x0 - 2 + c;
        float v = 0.f;
        if (ly >= 0 && ly < HP_ && gx >= 0 && gx < wlim) {
            v = x[((b * CI_ + ci) * H_ + part * HP_ + ly) * W_ + gx];
        }
        sIn[i] = v;
    }
    __syncthreads();

    float acc[TY][XS];
    #pragma unroll
    for (int o = 0; o < TY; ++o)
        #pragma unroll
        for (int j = 0; j < XS; ++j) acc[o][j] = 0.f;

    #pragma unroll 1
    for (int ci = 0; ci < CI_; ++ci) {
        float wgt[NTAPS];
        const float* wp = sW + ci * (NTAPS * CO_) + co;
        #pragma unroll
        for (int k = 0; k < NTAPS; ++k) wgt[k] = wp[k * CO_];

        const float* rb = sIn + ci * (SIN_ROWS * SIN_COLS) + xoff;
        #pragma unroll
        for (int r = 0; r < SIN_ROWS; ++r) {
            float v[12];
            const float4 a0 = *(const float4*)(rb + r * SIN_COLS);
            const float4 a1 = *(const float4*)(rb + r * SIN_COLS + 4);
            const float4 a2 = *(const float4*)(rb + r * SIN_COLS + 8);
            v[0]=a0.x; v[1]=a0.y; v[2]=a0.z; v[3]=a0.w;
            v[4]=a1.x; v[5]=a1.y; v[6]=a1.z; v[7]=a1.w;
            v[8]=a2.x; v[9]=a2.y; v[10]=a2.z; v[11]=a2.w;

            // out row o uses input rows o (ky0), o+1 (ky1), o+2 (ky2);
            // smem row r = input row (y0-2+r), out row o local = y0+o.
            if (r < TY) {                         // ky=0 taps for out row r
                #pragma unroll
                for (int kx = 0; kx < 5; ++kx)
                    #pragma unroll
                    for (int j = 0; j < XS; ++j)
                        acc[r][j] = fmaf(v[j + kx], wgt[kx], acc[r][j]);
            }
            if (r >= 1 && r < TY + 1) {           // ky=1 taps for out row r-1
                #pragma unroll
                for (int kx = 0; kx < 5; ++kx)
                    #pragma unroll
                    for (int j = 0; j < XS; ++j)
                        acc[r-1][j] = fmaf(v[j + kx], wgt[5 + kx], acc[r-1][j]);
            }
            if (r >= 2) {                         // ky=2 taps for out row r-2
                #pragma unroll
                for (int j = 0; j < XS; ++j) {
                    acc[r-2][j] = fmaf(v[j],     wgt[10], acc[r-2][j]);
                    acc[r-2][j] = fmaf(v[j + 1], wgt[11], acc[r-2][j]);
                    acc[r-2][j] = fmaf(v[j + 2], wgt[12], acc[r-2][j]);
                }
            }
        }
    }

    // ---- epilogue: bias, leaky-ReLU, width mask, vectorized store ----
    const float bz = __ldg(bias  + co);
    const float al = __ldg(alpha + co);
    #pragma unroll
    for (int o = 0; o < TY; ++o) {
        float vals[XS];
        #pragma unroll
        for (int j = 0; j < XS; ++j) {
            float y = acc[o][j] + bz;
            y = (y > 0.f) ? y : al * y;
            int gx = x0 + xoff + j;
            vals[j] = (gx < width) ? y : 0.f;
        }
        int base = ((b * CO_ + co) * H_ + gy0 + o) * W_ + x0 + xoff;
        *(float4*)(out + base)     = make_float4(vals[0], vals[1], vals[2], vals[3]);
        *(float4*)(out + base + 4) = make_float4(vals[4], vals[5], vals[6], vals[7]);
    }
}

// ---------------------------------------------------------------------------
// Launch
// ---------------------------------------------------------------------------
extern "C" void kernel_launch(void* const* d_in, const int* in_sizes, int n_in,
                              void* d_out, int out_size)
{
    const float* x      = (const float*)d_in[0];
    const float* weight = (const float*)d_in[1];
    const float* bias   = (const float*)d_in[2];
    const float* alpha  = (const float*)d_in[3];
    const int*   widths = (const int*)  d_in[4];
    float* out = (float*)d_out;

    (void)in_sizes; (void)n_in; (void)out_size;

    cudaFuncSetAttribute(conv_kernel,
                         cudaFuncAttributeMaxDynamicSharedMemorySize,
                         SMEM_BYTES);

    prep_weights<<<(SW_ELEMS + 255) / 256, 256>>>(weight);

    dim3 grid(W_ / TX, HP_ / TY, B_ * NPART);
    conv_kernel<<<grid, NTHREADS, SMEM_BYTES>>>(x, bias, alpha, widths, out);
}